// round 9
// baseline (speedup 1.0000x reference)
#include <cuda_runtime.h>
#include <cuda_fp16.h>
#include <math.h>

// Problem-fixed sizes: N=100000, E=1600000, D=128, EIG=32.
#define MAXN 100000
#define MAXE 1600000
#define FULLMASK 0xffffffffu

// Scratch (device globals — explicitly zeroed by k_init every call).
__device__ float g_me[MAXN];        // per-node motif embedding value
__device__ int   g_cnt[MAXN];       // histogram, then scatter cursor
__device__ int   g_off[MAXN + 1];   // CSR row offsets
__device__ float g_acc[3];          // sum(ab), sum(a2), sum(b2)
__device__ float g_par[2];          // [0]=exp(lambda0), [1]=c = gamma*sim
__device__ int2  g_edge[MAXE];      // (col, adj-as-int) sorted by row
__device__ uint2 g_vh[MAXN * 32];   // v packed as fp16 (4 halfs per uint2)

// ---- cache-policy-steered load helpers (sm_103a-legal cache_hint form) ----
__device__ __forceinline__ unsigned long long mk_policy_el() {
    unsigned long long pol;
    asm("createpolicy.fractional.L2::evict_last.b64 %0, 1.0;" : "=l"(pol));
    return pol;
}
__device__ __forceinline__ float4 ldg_el_f4(const float4* p,
                                            unsigned long long pol) {
    float4 r;
    asm("ld.global.nc.L2::cache_hint.v4.f32 {%0,%1,%2,%3},[%4],%5;"
        : "=f"(r.x), "=f"(r.y), "=f"(r.z), "=f"(r.w) : "l"(p), "l"(pol));
    return r;
}
__device__ __forceinline__ float ldg_el_f(const float* p,
                                          unsigned long long pol) {
    float r;
    asm("ld.global.nc.L2::cache_hint.f32 %0,[%1],%2;" : "=f"(r)
        : "l"(p), "l"(pol));
    return r;
}
__device__ __forceinline__ uint2 ldg_el_u2(const uint2* p,
                                           unsigned long long pol) {
    uint2 r;
    asm("ld.global.nc.L2::cache_hint.v2.u32 {%0,%1},[%2],%3;"
        : "=r"(r.x), "=r"(r.y) : "l"(p), "l"(pol));
    return r;
}

// ---------------------------------------------------------------------------
// K0: zero counters/accumulators, compute me[n] (proven protocol)
// ---------------------------------------------------------------------------
__global__ void k_init(const float* __restrict__ memb,
                       const int* __restrict__ mids, int n) {
    int i = blockIdx.x * blockDim.x + threadIdx.x;
    if (i == 0) { g_acc[0] = 0.f; g_acc[1] = 0.f; g_acc[2] = 0.f; }
    if (i < n) {
        g_me[i]  = memb[__ldcs(&mids[i])];
        g_cnt[i] = 0;
    }
}

// ---------------------------------------------------------------------------
// K0b: pack v into fp16 (streaming read/write)
// ---------------------------------------------------------------------------
__global__ void k_pack(const float4* __restrict__ v4, int n32) {
    for (int i = blockIdx.x * blockDim.x + threadIdx.x; i < n32;
         i += gridDim.x * blockDim.x) {
        float4 vv = __ldcs(&v4[i]);
        __half2 h0 = __floats2half2_rn(vv.x, vv.y);
        __half2 h1 = __floats2half2_rn(vv.z, vv.w);
        uint2 u;
        u.x = *reinterpret_cast<unsigned*>(&h0);
        u.y = *reinterpret_cast<unsigned*>(&h1);
        g_vh[i] = u;
    }
}

// ---------------------------------------------------------------------------
// K1: edge-level scalar reductions (cosine sim) + row histogram
// ---------------------------------------------------------------------------
__global__ void k_edge1(const int* __restrict__ row,
                        const int* __restrict__ col, int e) {
    float pab = 0.f, pa2 = 0.f, pb2 = 0.f;
    for (int i = blockIdx.x * blockDim.x + threadIdx.x; i < e;
         i += gridDim.x * blockDim.x) {
        int r = __ldcs(&row[i]), c = __ldcs(&col[i]);
        atomicAdd(&g_cnt[r], 1);
        float a = g_me[r], b = g_me[c];
        pab = fmaf(a, b, pab);
        pa2 = fmaf(a, a, pa2);
        pb2 = fmaf(b, b, pb2);
    }
#pragma unroll
    for (int o = 16; o; o >>= 1) {
        pab += __shfl_down_sync(FULLMASK, pab, o);
        pa2 += __shfl_down_sync(FULLMASK, pa2, o);
        pb2 += __shfl_down_sync(FULLMASK, pb2, o);
    }
    __shared__ float sb[3][8];
    int w = threadIdx.x >> 5, l = threadIdx.x & 31;
    if (!l) { sb[0][w] = pab; sb[1][w] = pa2; sb[2][w] = pb2; }
    __syncthreads();
    if (!threadIdx.x) {
        float t0 = 0.f, t1 = 0.f, t2 = 0.f;
        int nw = blockDim.x >> 5;
        for (int j = 0; j < nw; j++) { t0 += sb[0][j]; t1 += sb[1][j]; t2 += sb[2][j]; }
        atomicAdd(&g_acc[0], t0);
        atomicAdd(&g_acc[1], t1);
        atomicAdd(&g_acc[2], t2);
    }
}

// ---------------------------------------------------------------------------
// K2: exclusive scan — PARALLEL 3-level version (replaces the 149µs serial
// single-thread scan ncu exposed in R8). Thread partials -> warp shfl
// inclusive scan -> warp0 scans the 32 warp sums -> per-thread offsets.
// ---------------------------------------------------------------------------
__global__ void k_scan(const float* __restrict__ lambda0,
                       const float* __restrict__ gamma, int n, int e) {
    __shared__ int wsum[32];
    int t = threadIdx.x;            // 1024 threads
    int lane = t & 31, warp = t >> 5;
    int chunk = (n + 1023) / 1024;
    int b = t * chunk;
    int en = b + chunk; if (en > n) en = n;
    int s = 0;
    for (int i = b; i < en; i++) s += g_cnt[i];
    int inc = s;
#pragma unroll
    for (int o = 1; o < 32; o <<= 1) {
        int u = __shfl_up_sync(FULLMASK, inc, o);
        if (lane >= o) inc += u;
    }
    if (lane == 31) wsum[warp] = inc;
    __syncthreads();
    if (warp == 0) {
        int v = wsum[lane];
        int winc = v;
#pragma unroll
        for (int o = 1; o < 32; o <<= 1) {
            int u = __shfl_up_sync(FULLMASK, winc, o);
            if (lane >= o) winc += u;
        }
        wsum[lane] = winc - v;   // exclusive warp base
    }
    __syncthreads();
    int run = wsum[warp] + (inc - s);   // exclusive prefix for this thread
    for (int i = b; i < en; i++) {
        int v = g_cnt[i];
        g_off[i] = run;
        g_cnt[i] = run;  // cursor for the scatter pass
        run += v;
    }
    if (!t) {
        g_off[n] = e;
        float sab = g_acc[0], sa2 = g_acc[1], sb2 = g_acc[2];
        float na = fmaxf(sqrtf(sa2), 1e-8f);
        float nb = fmaxf(sqrtf(sb2), 1e-8f);
        g_par[0] = expf(lambda0[0]);
        g_par[1] = gamma[0] * (sab / (na * nb));
    }
}

// ---------------------------------------------------------------------------
// K3: counting-sort scatter, clamped write position (tripwire).
// ---------------------------------------------------------------------------
__global__ void k_scatter(const int* __restrict__ row,
                          const int* __restrict__ col,
                          const float* __restrict__ adj, int e) {
    for (int i = blockIdx.x * blockDim.x + threadIdx.x; i < e;
         i += gridDim.x * blockDim.x) {
        int pos = atomicAdd(&g_cnt[__ldcs(&row[i])], 1);
        pos = min(max(pos, 0), MAXE - 1);
        g_edge[pos] = make_int2(__ldcs(&col[i]), __float_as_int(__ldcs(&adj[i])));
    }
}

// ---------------------------------------------------------------------------
// K4: fused per-row kernel (R8 verbatim — single-variable round).
// ---------------------------------------------------------------------------
__global__ void __launch_bounds__(256)
k_main(const float4* __restrict__ q4, const float4* __restrict__ k4p,
       const float* __restrict__ eigs, float4* __restrict__ out4,
       int n, int e) {
    int wid  = (blockIdx.x * blockDim.x + threadIdx.x) >> 5;
    int lane = threadIdx.x & 31;
    if (wid >= n) return;
    int start = g_off[wid];
    int end   = g_off[wid + 1];
    start = min(max(start, 0), e);
    end   = min(max(end, start), e);

    float4 zero = make_float4(0.f, 0.f, 0.f, 0.f);
    if (start == end) {                 // empty segment -> zeros
        out4[wid * 32 + lane] = zero;
        return;
    }
    unsigned long long pol = mk_policy_el();
    const float inv = 0.08838834764831845f;  // 1/sqrt(128)
    float c = g_par[1];

    float4 q  = __ldcs(&q4[wid * 32 + lane]);           // single-use stream
    float4 qs = make_float4(q.x * inv, q.y * inv, q.z * inv, q.w * inv);
    float  ler = g_par[0] * ldg_el_f(&eigs[wid * 32 + lane], pol);

    float  m0 = -INFINITY, z0 = 0.f;
    float  m1 = -INFINITY, z1 = 0.f;
    float4 a0 = zero, a1 = zero;

    for (int base = start; base < end; base += 32) {
        int nb = end - base; if (nb > 32) nb = 32;
        int2 ea = (lane < nb) ? __ldcs(&g_edge[base + lane]) : make_int2(0, 0);
        int   bc = min(max(ea.x, 0), n - 1);
        float ba = __int_as_float(ea.y);

        // depth-1 software pipeline (R2 structure)
        int    ci = __shfl_sync(FULLMASK, bc, 0);
        float4 kk = ldg_el_f4(&k4p[ci * 32 + lane], pol);
        float  ec = ldg_el_f(&eigs[ci * 32 + lane], pol);
        uint2  vu = ldg_el_u2(&g_vh[ci * 32 + lane], pol);

        for (int i = 0; i < nb; i++) {
            int j = i + 1; if (j >= nb) j = i;
            int    cn  = __shfl_sync(FULLMASK, bc, j);
            float  adj = __shfl_sync(FULLMASK, ba, i);
            float4 kk2 = ldg_el_f4(&k4p[cn * 32 + lane], pol);
            float  ec2 = ldg_el_f(&eigs[cn * 32 + lane], pol);
            uint2  vu2 = ldg_el_u2(&g_vh[cn * 32 + lane], pol);

            float part = fmaf(qs.x, kk.x,
                         fmaf(qs.y, kk.y,
                         fmaf(qs.z, kk.z,
                         fmaf(qs.w, kk.w, ler * ec))));
#pragma unroll
            for (int o = 16; o; o >>= 1)
                part += __shfl_xor_sync(FULLMASK, part, o);

            // unpack fp16 v
            __half2 h0 = *reinterpret_cast<__half2*>(&vu.x);
            __half2 h1 = *reinterpret_cast<__half2*>(&vu.y);
            float2 v01 = __half22float2(h0);
            float2 v23 = __half22float2(h1);

            // branch 0: online softmax of s0
            float nm0 = fmaxf(m0, part);
            float sc0 = __expf(m0 - nm0);
            float w0  = __expf(part - nm0);
            z0   = fmaf(z0, sc0, w0);
            a0.x = fmaf(a0.x, sc0, w0 * v01.x);
            a0.y = fmaf(a0.y, sc0, w0 * v01.y);
            a0.z = fmaf(a0.z, sc0, w0 * v23.x);
            a0.w = fmaf(a0.w, sc0, w0 * v23.y);
            m0 = nm0;

            // branch 1: online softmax of c*adj
            float s1  = c * adj;
            float nm1 = fmaxf(m1, s1);
            float sc1 = __expf(m1 - nm1);
            float w1  = __expf(s1 - nm1);
            z1   = fmaf(z1, sc1, w1);
            a1.x = fmaf(a1.x, sc1, w1 * v01.x);
            a1.y = fmaf(a1.y, sc1, w1 * v01.y);
            a1.z = fmaf(a1.z, sc1, w1 * v23.x);
            a1.w = fmaf(a1.w, sc1, w1 * v23.y);
            m1 = nm1;

            kk = kk2; ec = ec2; vu = vu2;
        }
    }

    float i0 = 0.5f / z0;
    float i1 = 0.5f / z1;
    float4 o;
    o.x = fmaf(a0.x, i0, a1.x * i1);
    o.y = fmaf(a0.y, i0, a1.y * i1);
    o.z = fmaf(a0.z, i0, a1.z * i1);
    o.w = fmaf(a0.w, i0, a1.w * i1);
    __stcs(&out4[wid * 32 + lane], o);
}

// ---------------------------------------------------------------------------
extern "C" void kernel_launch(void* const* d_in, const int* in_sizes, int n_in,
                              void* d_out, int out_size) {
    const float* q       = (const float*)d_in[0];
    const float* k       = (const float*)d_in[1];
    const float* v       = (const float*)d_in[2];
    const float* eigs    = (const float*)d_in[3];
    const float* adj     = (const float*)d_in[4];
    const float* lambda0 = (const float*)d_in[5];
    const float* gamma   = (const float*)d_in[6];
    const float* memb    = (const float*)d_in[7];
    const int*   row     = (const int*)d_in[8];
    const int*   col     = (const int*)d_in[9];
    const int*   mids    = (const int*)d_in[10];

    int n = in_sizes[10];  // N
    int e = in_sizes[8];   // E

    k_init<<<(n + 255) / 256, 256>>>(memb, mids, n);
    k_pack<<<2048, 256>>>((const float4*)v, n * 32);
    k_edge1<<<2048, 256>>>(row, col, e);
    k_scan<<<1, 1024>>>(lambda0, gamma, n, e);
    k_scatter<<<2048, 256>>>(row, col, adj, e);
    k_main<<<(n * 32 + 255) / 256, 256>>>(
        (const float4*)q, (const float4*)k, eigs,
        (float4*)d_out, n, e);
}

// round 10
// speedup vs baseline: 2.0474x; 2.0474x over previous
#include <cuda_runtime.h>
#include <cuda_fp16.h>
#include <math.h>

// Problem-fixed sizes: N=100000, E=1600000, D=128, EIG=32.
#define MAXN 100000
#define MAXE 1600000
#define FULLMASK 0xffffffffu
#define SCAN_BLOCKS 128
#define SCAN_THREADS 1024   // 128*1024 = 131072 >= N, one element per thread

// Scratch (device globals — explicitly zeroed by k_init every call).
__device__ float g_me[MAXN];        // per-node motif embedding value
__device__ int   g_cnt[MAXN];       // histogram, then scatter cursor
__device__ int   g_off[MAXN + 1];   // CSR row offsets
__device__ float g_acc[3];          // sum(ab), sum(a2), sum(b2)
__device__ float g_par[2];          // [0]=exp(lambda0), [1]=c = gamma*sim
__device__ int2  g_edge[MAXE];      // (col, adj-as-int) sorted by row
__device__ uint2 g_vh[MAXN * 32];   // v packed as fp16 (4 halfs per uint2)
__device__ int   g_bsum[SCAN_BLOCKS];   // per-block histogram sums
__device__ int   g_bbase[SCAN_BLOCKS];  // exclusive bases per block

// ---- cache-policy-steered load helpers (sm_103a-legal cache_hint form) ----
__device__ __forceinline__ unsigned long long mk_policy_el() {
    unsigned long long pol;
    asm("createpolicy.fractional.L2::evict_last.b64 %0, 1.0;" : "=l"(pol));
    return pol;
}
__device__ __forceinline__ float4 ldg_el_f4(const float4* p,
                                            unsigned long long pol) {
    float4 r;
    asm("ld.global.nc.L2::cache_hint.v4.f32 {%0,%1,%2,%3},[%4],%5;"
        : "=f"(r.x), "=f"(r.y), "=f"(r.z), "=f"(r.w) : "l"(p), "l"(pol));
    return r;
}
__device__ __forceinline__ float ldg_el_f(const float* p,
                                          unsigned long long pol) {
    float r;
    asm("ld.global.nc.L2::cache_hint.f32 %0,[%1],%2;" : "=f"(r)
        : "l"(p), "l"(pol));
    return r;
}
__device__ __forceinline__ uint2 ldg_el_u2(const uint2* p,
                                           unsigned long long pol) {
    uint2 r;
    asm("ld.global.nc.L2::cache_hint.v2.u32 {%0,%1},[%2],%3;"
        : "=r"(r.x), "=r"(r.y) : "l"(p), "l"(pol));
    return r;
}

// ---------------------------------------------------------------------------
// K0: zero counters/accumulators, compute me[n] (proven protocol)
// ---------------------------------------------------------------------------
__global__ void k_init(const float* __restrict__ memb,
                       const int* __restrict__ mids, int n) {
    int i = blockIdx.x * blockDim.x + threadIdx.x;
    if (i == 0) { g_acc[0] = 0.f; g_acc[1] = 0.f; g_acc[2] = 0.f; }
    if (i < n) {
        g_me[i]  = memb[__ldcs(&mids[i])];
        g_cnt[i] = 0;
    }
}

// ---------------------------------------------------------------------------
// K0b: pack v into fp16 (streaming read/write)
// ---------------------------------------------------------------------------
__global__ void k_pack(const float4* __restrict__ v4, int n32) {
    for (int i = blockIdx.x * blockDim.x + threadIdx.x; i < n32;
         i += gridDim.x * blockDim.x) {
        float4 vv = __ldcs(&v4[i]);
        __half2 h0 = __floats2half2_rn(vv.x, vv.y);
        __half2 h1 = __floats2half2_rn(vv.z, vv.w);
        uint2 u;
        u.x = *reinterpret_cast<unsigned*>(&h0);
        u.y = *reinterpret_cast<unsigned*>(&h1);
        g_vh[i] = u;
    }
}

// ---------------------------------------------------------------------------
// K1: edge-level scalar reductions (cosine sim) + row histogram
// ---------------------------------------------------------------------------
__global__ void k_edge1(const int* __restrict__ row,
                        const int* __restrict__ col, int e) {
    float pab = 0.f, pa2 = 0.f, pb2 = 0.f;
    for (int i = blockIdx.x * blockDim.x + threadIdx.x; i < e;
         i += gridDim.x * blockDim.x) {
        int r = __ldcs(&row[i]), c = __ldcs(&col[i]);
        atomicAdd(&g_cnt[r], 1);
        float a = g_me[r], b = g_me[c];
        pab = fmaf(a, b, pab);
        pa2 = fmaf(a, a, pa2);
        pb2 = fmaf(b, b, pb2);
    }
#pragma unroll
    for (int o = 16; o; o >>= 1) {
        pab += __shfl_down_sync(FULLMASK, pab, o);
        pa2 += __shfl_down_sync(FULLMASK, pa2, o);
        pb2 += __shfl_down_sync(FULLMASK, pb2, o);
    }
    __shared__ float sb[3][8];
    int w = threadIdx.x >> 5, l = threadIdx.x & 31;
    if (!l) { sb[0][w] = pab; sb[1][w] = pa2; sb[2][w] = pb2; }
    __syncthreads();
    if (!threadIdx.x) {
        float t0 = 0.f, t1 = 0.f, t2 = 0.f;
        int nw = blockDim.x >> 5;
        for (int j = 0; j < nw; j++) { t0 += sb[0][j]; t1 += sb[1][j]; t2 += sb[2][j]; }
        atomicAdd(&g_acc[0], t0);
        atomicAdd(&g_acc[1], t1);
        atomicAdd(&g_acc[2], t2);
    }
}

// ---------------------------------------------------------------------------
// Scan stage A: per-block COALESCED reduce of g_cnt (i = blk*1024 + tid).
// ---------------------------------------------------------------------------
__global__ void k_scan_a(int n) {
    __shared__ int wsum[32];
    int t = threadIdx.x, lane = t & 31, warp = t >> 5;
    int i = blockIdx.x * SCAN_THREADS + t;
    int v = (i < n) ? g_cnt[i] : 0;
    int s = v;
#pragma unroll
    for (int o = 16; o; o >>= 1) s += __shfl_down_sync(FULLMASK, s, o);
    if (!lane) wsum[warp] = s;
    __syncthreads();
    if (warp == 0) {
        int x = wsum[lane];
#pragma unroll
        for (int o = 16; o; o >>= 1) x += __shfl_down_sync(FULLMASK, x, o);
        if (!lane) g_bsum[blockIdx.x] = x;
    }
}

// ---------------------------------------------------------------------------
// Scan stage B: one tiny block scans the 128 block sums; computes scalars.
// ---------------------------------------------------------------------------
__global__ void k_scan_b(const float* __restrict__ lambda0,
                         const float* __restrict__ gamma, int n, int e) {
    __shared__ int ws[4];
    int t = threadIdx.x, lane = t & 31, warp = t >> 5;   // 128 threads
    int v = g_bsum[t];
    int inc = v;
#pragma unroll
    for (int o = 1; o < 32; o <<= 1) {
        int u = __shfl_up_sync(FULLMASK, inc, o);
        if (lane >= o) inc += u;
    }
    if (lane == 31) ws[warp] = inc;
    __syncthreads();
    if (t == 0) {
        int run = 0;
        for (int j = 0; j < 4; j++) { int x = ws[j]; ws[j] = run; run += x; }
        g_off[n] = e;
        float sab = g_acc[0], sa2 = g_acc[1], sb2 = g_acc[2];
        float na = fmaxf(sqrtf(sa2), 1e-8f);
        float nb = fmaxf(sqrtf(sb2), 1e-8f);
        g_par[0] = expf(lambda0[0]);
        g_par[1] = gamma[0] * (sab / (na * nb));
    }
    __syncthreads();
    g_bbase[t] = ws[warp] + (inc - v);
}

// ---------------------------------------------------------------------------
// Scan stage C: per-block COALESCED exclusive scan + base -> g_off, cursor.
// ---------------------------------------------------------------------------
__global__ void k_scan_c(int n) {
    __shared__ int wsum[32];
    int t = threadIdx.x, lane = t & 31, warp = t >> 5;
    int i = blockIdx.x * SCAN_THREADS + t;
    int v = (i < n) ? g_cnt[i] : 0;
    int inc = v;
#pragma unroll
    for (int o = 1; o < 32; o <<= 1) {
        int u = __shfl_up_sync(FULLMASK, inc, o);
        if (lane >= o) inc += u;
    }
    if (lane == 31) wsum[warp] = inc;
    __syncthreads();
    if (warp == 0) {
        int x = wsum[lane];
        int winc = x;
#pragma unroll
        for (int o = 1; o < 32; o <<= 1) {
            int u = __shfl_up_sync(FULLMASK, winc, o);
            if (lane >= o) winc += u;
        }
        wsum[lane] = winc - x;   // exclusive warp base
    }
    __syncthreads();
    int run = g_bbase[blockIdx.x] + wsum[warp] + (inc - v);
    if (i < n) {
        g_off[i] = run;
        g_cnt[i] = run;   // cursor for the scatter pass
    }
}

// ---------------------------------------------------------------------------
// K3: counting-sort scatter, clamped write position (tripwire).
// ---------------------------------------------------------------------------
__global__ void k_scatter(const int* __restrict__ row,
                          const int* __restrict__ col,
                          const float* __restrict__ adj, int e) {
    for (int i = blockIdx.x * blockDim.x + threadIdx.x; i < e;
         i += gridDim.x * blockDim.x) {
        int pos = atomicAdd(&g_cnt[__ldcs(&row[i])], 1);
        pos = min(max(pos, 0), MAXE - 1);
        g_edge[pos] = make_int2(__ldcs(&col[i]), __float_as_int(__ldcs(&adj[i])));
    }
}

// ---------------------------------------------------------------------------
// K4: fused per-row kernel (R8 verbatim).
// ---------------------------------------------------------------------------
__global__ void __launch_bounds__(256)
k_main(const float4* __restrict__ q4, const float4* __restrict__ k4p,
       const float* __restrict__ eigs, float4* __restrict__ out4,
       int n, int e) {
    int wid  = (blockIdx.x * blockDim.x + threadIdx.x) >> 5;
    int lane = threadIdx.x & 31;
    if (wid >= n) return;
    int start = g_off[wid];
    int end   = g_off[wid + 1];
    start = min(max(start, 0), e);
    end   = min(max(end, start), e);

    float4 zero = make_float4(0.f, 0.f, 0.f, 0.f);
    if (start == end) {                 // empty segment -> zeros
        out4[wid * 32 + lane] = zero;
        return;
    }
    unsigned long long pol = mk_policy_el();
    const float inv = 0.08838834764831845f;  // 1/sqrt(128)
    float c = g_par[1];

    float4 q  = __ldcs(&q4[wid * 32 + lane]);           // single-use stream
    float4 qs = make_float4(q.x * inv, q.y * inv, q.z * inv, q.w * inv);
    float  ler = g_par[0] * ldg_el_f(&eigs[wid * 32 + lane], pol);

    float  m0 = -INFINITY, z0 = 0.f;
    float  m1 = -INFINITY, z1 = 0.f;
    float4 a0 = zero, a1 = zero;

    for (int base = start; base < end; base += 32) {
        int nb = end - base; if (nb > 32) nb = 32;
        int2 ea = (lane < nb) ? __ldcs(&g_edge[base + lane]) : make_int2(0, 0);
        int   bc = min(max(ea.x, 0), n - 1);
        float ba = __int_as_float(ea.y);

        // depth-1 software pipeline (R2 structure)
        int    ci = __shfl_sync(FULLMASK, bc, 0);
        float4 kk = ldg_el_f4(&k4p[ci * 32 + lane], pol);
        float  ec = ldg_el_f(&eigs[ci * 32 + lane], pol);
        uint2  vu = ldg_el_u2(&g_vh[ci * 32 + lane], pol);

        for (int i = 0; i < nb; i++) {
            int j = i + 1; if (j >= nb) j = i;
            int    cn  = __shfl_sync(FULLMASK, bc, j);
            float  adj = __shfl_sync(FULLMASK, ba, i);
            float4 kk2 = ldg_el_f4(&k4p[cn * 32 + lane], pol);
            float  ec2 = ldg_el_f(&eigs[cn * 32 + lane], pol);
            uint2  vu2 = ldg_el_u2(&g_vh[cn * 32 + lane], pol);

            float part = fmaf(qs.x, kk.x,
                         fmaf(qs.y, kk.y,
                         fmaf(qs.z, kk.z,
                         fmaf(qs.w, kk.w, ler * ec))));
#pragma unroll
            for (int o = 16; o; o >>= 1)
                part += __shfl_xor_sync(FULLMASK, part, o);

            // unpack fp16 v
            __half2 h0 = *reinterpret_cast<__half2*>(&vu.x);
            __half2 h1 = *reinterpret_cast<__half2*>(&vu.y);
            float2 v01 = __half22float2(h0);
            float2 v23 = __half22float2(h1);

            // branch 0: online softmax of s0
            float nm0 = fmaxf(m0, part);
            float sc0 = __expf(m0 - nm0);
            float w0  = __expf(part - nm0);
            z0   = fmaf(z0, sc0, w0);
            a0.x = fmaf(a0.x, sc0, w0 * v01.x);
            a0.y = fmaf(a0.y, sc0, w0 * v01.y);
            a0.z = fmaf(a0.z, sc0, w0 * v23.x);
            a0.w = fmaf(a0.w, sc0, w0 * v23.y);
            m0 = nm0;

            // branch 1: online softmax of c*adj
            float s1  = c * adj;
            float nm1 = fmaxf(m1, s1);
            float sc1 = __expf(m1 - nm1);
            float w1  = __expf(s1 - nm1);
            z1   = fmaf(z1, sc1, w1);
            a1.x = fmaf(a1.x, sc1, w1 * v01.x);
            a1.y = fmaf(a1.y, sc1, w1 * v01.y);
            a1.z = fmaf(a1.z, sc1, w1 * v23.x);
            a1.w = fmaf(a1.w, sc1, w1 * v23.y);
            m1 = nm1;

            kk = kk2; ec = ec2; vu = vu2;
        }
    }

    float i0 = 0.5f / z0;
    float i1 = 0.5f / z1;
    float4 o;
    o.x = fmaf(a0.x, i0, a1.x * i1);
    o.y = fmaf(a0.y, i0, a1.y * i1);
    o.z = fmaf(a0.z, i0, a1.z * i1);
    o.w = fmaf(a0.w, i0, a1.w * i1);
    __stcs(&out4[wid * 32 + lane], o);
}

// ---------------------------------------------------------------------------
extern "C" void kernel_launch(void* const* d_in, const int* in_sizes, int n_in,
                              void* d_out, int out_size) {
    const float* q       = (const float*)d_in[0];
    const float* k       = (const float*)d_in[1];
    const float* v       = (const float*)d_in[2];
    const float* eigs    = (const float*)d_in[3];
    const float* adj     = (const float*)d_in[4];
    const float* lambda0 = (const float*)d_in[5];
    const float* gamma   = (const float*)d_in[6];
    const float* memb    = (const float*)d_in[7];
    const int*   row     = (const int*)d_in[8];
    const int*   col     = (const int*)d_in[9];
    const int*   mids    = (const int*)d_in[10];

    int n = in_sizes[10];  // N
    int e = in_sizes[8];   // E

    k_init<<<(n + 255) / 256, 256>>>(memb, mids, n);
    k_pack<<<2048, 256>>>((const float4*)v, n * 32);
    k_edge1<<<2048, 256>>>(row, col, e);
    k_scan_a<<<SCAN_BLOCKS, SCAN_THREADS>>>(n);
    k_scan_b<<<1, SCAN_BLOCKS>>>(lambda0, gamma, n, e);
    k_scan_c<<<SCAN_BLOCKS, SCAN_THREADS>>>(n);
    k_scatter<<<2048, 256>>>(row, col, adj, e);
    k_main<<<(n * 32 + 255) / 256, 256>>>(
        (const float4*)q, (const float4*)k, eigs,
        (float4*)d_out, n, e);
}

// round 11
// speedup vs baseline: 2.3104x; 1.1285x over previous
#include <cuda_runtime.h>
#include <cuda_fp16.h>
#include <math.h>

// Problem-fixed sizes: N=100000, E=1600000, D=128, EIG=32.
#define MAXN 100000
#define MAXE 1600000
#define FULLMASK 0xffffffffu
#define SCAN_BLOCKS 128
#define SCAN_THREADS 1024   // 128*1024 = 131072 >= N, one element per thread

// Scratch (device globals — explicitly zeroed by k_init every call).
__device__ float g_me[MAXN];        // per-node motif embedding value
__device__ int   g_cnt[MAXN];       // histogram, then scatter cursor
__device__ int   g_off[MAXN + 1];   // CSR row offsets
__device__ float g_acc[3];          // sum(ab), sum(a2), sum(b2)
__device__ float g_par[2];          // [0]=exp(lambda0), [1]=c = gamma*sim
__device__ int2  g_edge[MAXE];      // (col, adj-as-int) sorted by row
__device__ uint2 g_vh[MAXN * 32];   // v packed as fp16 (4 halfs per uint2)
__device__ uint2 g_kh[MAXN * 32];   // k packed as fp16 (4 halfs per uint2)
__device__ int   g_bsum[SCAN_BLOCKS];   // per-block histogram sums
__device__ int   g_bbase[SCAN_BLOCKS];  // exclusive bases per block

// ---- cache-policy-steered load helpers (sm_103a-legal cache_hint form) ----
__device__ __forceinline__ unsigned long long mk_policy_el() {
    unsigned long long pol;
    asm("createpolicy.fractional.L2::evict_last.b64 %0, 1.0;" : "=l"(pol));
    return pol;
}
__device__ __forceinline__ float ldg_el_f(const float* p,
                                          unsigned long long pol) {
    float r;
    asm("ld.global.nc.L2::cache_hint.f32 %0,[%1],%2;" : "=f"(r)
        : "l"(p), "l"(pol));
    return r;
}
__device__ __forceinline__ uint2 ldg_el_u2(const uint2* p,
                                           unsigned long long pol) {
    uint2 r;
    asm("ld.global.nc.L2::cache_hint.v2.u32 {%0,%1},[%2],%3;"
        : "=r"(r.x), "=r"(r.y) : "l"(p), "l"(pol));
    return r;
}

// ---------------------------------------------------------------------------
// K0: zero counters/accumulators, compute me[n] (proven protocol)
// ---------------------------------------------------------------------------
__global__ void k_init(const float* __restrict__ memb,
                       const int* __restrict__ mids, int n) {
    int i = blockIdx.x * blockDim.x + threadIdx.x;
    if (i == 0) { g_acc[0] = 0.f; g_acc[1] = 0.f; g_acc[2] = 0.f; }
    if (i < n) {
        g_me[i]  = memb[__ldcs(&mids[i])];
        g_cnt[i] = 0;
    }
}

// ---------------------------------------------------------------------------
// K0b: pack k AND v into fp16 (streaming read/write)
// ---------------------------------------------------------------------------
__global__ void k_pack(const float4* __restrict__ k4,
                       const float4* __restrict__ v4, int n32) {
    for (int i = blockIdx.x * blockDim.x + threadIdx.x; i < n32;
         i += gridDim.x * blockDim.x) {
        float4 kk = __ldcs(&k4[i]);
        __half2 kh0 = __floats2half2_rn(kk.x, kk.y);
        __half2 kh1 = __floats2half2_rn(kk.z, kk.w);
        uint2 ku;
        ku.x = *reinterpret_cast<unsigned*>(&kh0);
        ku.y = *reinterpret_cast<unsigned*>(&kh1);
        g_kh[i] = ku;

        float4 vv = __ldcs(&v4[i]);
        __half2 h0 = __floats2half2_rn(vv.x, vv.y);
        __half2 h1 = __floats2half2_rn(vv.z, vv.w);
        uint2 u;
        u.x = *reinterpret_cast<unsigned*>(&h0);
        u.y = *reinterpret_cast<unsigned*>(&h1);
        g_vh[i] = u;
    }
}

// ---------------------------------------------------------------------------
// K1: edge-level scalar reductions (cosine sim) + row histogram
// ---------------------------------------------------------------------------
__global__ void k_edge1(const int* __restrict__ row,
                        const int* __restrict__ col, int e) {
    float pab = 0.f, pa2 = 0.f, pb2 = 0.f;
    for (int i = blockIdx.x * blockDim.x + threadIdx.x; i < e;
         i += gridDim.x * blockDim.x) {
        int r = __ldcs(&row[i]), c = __ldcs(&col[i]);
        atomicAdd(&g_cnt[r], 1);
        float a = g_me[r], b = g_me[c];
        pab = fmaf(a, b, pab);
        pa2 = fmaf(a, a, pa2);
        pb2 = fmaf(b, b, pb2);
    }
#pragma unroll
    for (int o = 16; o; o >>= 1) {
        pab += __shfl_down_sync(FULLMASK, pab, o);
        pa2 += __shfl_down_sync(FULLMASK, pa2, o);
        pb2 += __shfl_down_sync(FULLMASK, pb2, o);
    }
    __shared__ float sb[3][8];
    int w = threadIdx.x >> 5, l = threadIdx.x & 31;
    if (!l) { sb[0][w] = pab; sb[1][w] = pa2; sb[2][w] = pb2; }
    __syncthreads();
    if (!threadIdx.x) {
        float t0 = 0.f, t1 = 0.f, t2 = 0.f;
        int nw = blockDim.x >> 5;
        for (int j = 0; j < nw; j++) { t0 += sb[0][j]; t1 += sb[1][j]; t2 += sb[2][j]; }
        atomicAdd(&g_acc[0], t0);
        atomicAdd(&g_acc[1], t1);
        atomicAdd(&g_acc[2], t2);
    }
}

// ---------------------------------------------------------------------------
// Scan stage A: per-block COALESCED reduce of g_cnt.
// ---------------------------------------------------------------------------
__global__ void k_scan_a(int n) {
    __shared__ int wsum[32];
    int t = threadIdx.x, lane = t & 31, warp = t >> 5;
    int i = blockIdx.x * SCAN_THREADS + t;
    int v = (i < n) ? g_cnt[i] : 0;
    int s = v;
#pragma unroll
    for (int o = 16; o; o >>= 1) s += __shfl_down_sync(FULLMASK, s, o);
    if (!lane) wsum[warp] = s;
    __syncthreads();
    if (warp == 0) {
        int x = wsum[lane];
#pragma unroll
        for (int o = 16; o; o >>= 1) x += __shfl_down_sync(FULLMASK, x, o);
        if (!lane) g_bsum[blockIdx.x] = x;
    }
}

// ---------------------------------------------------------------------------
// Scan stage B: one tiny block scans the 128 block sums; computes scalars.
// ---------------------------------------------------------------------------
__global__ void k_scan_b(const float* __restrict__ lambda0,
                         const float* __restrict__ gamma, int n, int e) {
    __shared__ int ws[4];
    int t = threadIdx.x, lane = t & 31, warp = t >> 5;   // 128 threads
    int v = g_bsum[t];
    int inc = v;
#pragma unroll
    for (int o = 1; o < 32; o <<= 1) {
        int u = __shfl_up_sync(FULLMASK, inc, o);
        if (lane >= o) inc += u;
    }
    if (lane == 31) ws[warp] = inc;
    __syncthreads();
    if (t == 0) {
        int run = 0;
        for (int j = 0; j < 4; j++) { int x = ws[j]; ws[j] = run; run += x; }
        g_off[n] = e;
        float sab = g_acc[0], sa2 = g_acc[1], sb2 = g_acc[2];
        float na = fmaxf(sqrtf(sa2), 1e-8f);
        float nb = fmaxf(sqrtf(sb2), 1e-8f);
        g_par[0] = expf(lambda0[0]);
        g_par[1] = gamma[0] * (sab / (na * nb));
    }
    __syncthreads();
    g_bbase[t] = ws[warp] + (inc - v);
}

// ---------------------------------------------------------------------------
// Scan stage C: per-block COALESCED exclusive scan + base -> g_off, cursor.
// ---------------------------------------------------------------------------
__global__ void k_scan_c(int n) {
    __shared__ int wsum[32];
    int t = threadIdx.x, lane = t & 31, warp = t >> 5;
    int i = blockIdx.x * SCAN_THREADS + t;
    int v = (i < n) ? g_cnt[i] : 0;
    int inc = v;
#pragma unroll
    for (int o = 1; o < 32; o <<= 1) {
        int u = __shfl_up_sync(FULLMASK, inc, o);
        if (lane >= o) inc += u;
    }
    if (lane == 31) wsum[warp] = inc;
    __syncthreads();
    if (warp == 0) {
        int x = wsum[lane];
        int winc = x;
#pragma unroll
        for (int o = 1; o < 32; o <<= 1) {
            int u = __shfl_up_sync(FULLMASK, winc, o);
            if (lane >= o) winc += u;
        }
        wsum[lane] = winc - x;   // exclusive warp base
    }
    __syncthreads();
    int run = g_bbase[blockIdx.x] + wsum[warp] + (inc - v);
    if (i < n) {
        g_off[i] = run;
        g_cnt[i] = run;   // cursor for the scatter pass
    }
}

// ---------------------------------------------------------------------------
// K3: counting-sort scatter, clamped write position (tripwire).
// ---------------------------------------------------------------------------
__global__ void k_scatter(const int* __restrict__ row,
                          const int* __restrict__ col,
                          const float* __restrict__ adj, int e) {
    for (int i = blockIdx.x * blockDim.x + threadIdx.x; i < e;
         i += gridDim.x * blockDim.x) {
        int pos = atomicAdd(&g_cnt[__ldcs(&row[i])], 1);
        pos = min(max(pos, 0), MAXE - 1);
        g_edge[pos] = make_int2(__ldcs(&col[i]), __float_as_int(__ldcs(&adj[i])));
    }
}

// ---------------------------------------------------------------------------
// K4: fused per-row kernel (R10 structure; k gather now fp16 like v).
// Per-edge gather: k 256B + eig 128B + v 256B = 640B, footprint 64MB < L2.
// ---------------------------------------------------------------------------
__global__ void __launch_bounds__(256)
k_main(const float4* __restrict__ q4, const float* __restrict__ eigs,
       float4* __restrict__ out4, int n, int e) {
    int wid  = (blockIdx.x * blockDim.x + threadIdx.x) >> 5;
    int lane = threadIdx.x & 31;
    if (wid >= n) return;
    int start = g_off[wid];
    int end   = g_off[wid + 1];
    start = min(max(start, 0), e);
    end   = min(max(end, start), e);

    float4 zero = make_float4(0.f, 0.f, 0.f, 0.f);
    if (start == end) {                 // empty segment -> zeros
        out4[wid * 32 + lane] = zero;
        return;
    }
    unsigned long long pol = mk_policy_el();
    const float inv = 0.08838834764831845f;  // 1/sqrt(128)
    float c = g_par[1];

    float4 q  = __ldcs(&q4[wid * 32 + lane]);           // single-use stream
    float4 qs = make_float4(q.x * inv, q.y * inv, q.z * inv, q.w * inv);
    float  ler = g_par[0] * ldg_el_f(&eigs[wid * 32 + lane], pol);

    float  m0 = -INFINITY, z0 = 0.f;
    float  m1 = -INFINITY, z1 = 0.f;
    float4 a0 = zero, a1 = zero;

    for (int base = start; base < end; base += 32) {
        int nb = end - base; if (nb > 32) nb = 32;
        int2 ea = (lane < nb) ? __ldcs(&g_edge[base + lane]) : make_int2(0, 0);
        int   bc = min(max(ea.x, 0), n - 1);
        float ba = __int_as_float(ea.y);

        // depth-1 software pipeline
        int    ci = __shfl_sync(FULLMASK, bc, 0);
        uint2  ku = ldg_el_u2(&g_kh[ci * 32 + lane], pol);
        float  ec = ldg_el_f(&eigs[ci * 32 + lane], pol);
        uint2  vu = ldg_el_u2(&g_vh[ci * 32 + lane], pol);

        for (int i = 0; i < nb; i++) {
            int j = i + 1; if (j >= nb) j = i;
            int    cn  = __shfl_sync(FULLMASK, bc, j);
            float  adj = __shfl_sync(FULLMASK, ba, i);
            uint2  ku2 = ldg_el_u2(&g_kh[cn * 32 + lane], pol);
            float  ec2 = ldg_el_f(&eigs[cn * 32 + lane], pol);
            uint2  vu2 = ldg_el_u2(&g_vh[cn * 32 + lane], pol);

            // unpack fp16 k
            __half2 kh0 = *reinterpret_cast<__half2*>(&ku.x);
            __half2 kh1 = *reinterpret_cast<__half2*>(&ku.y);
            float2 k01 = __half22float2(kh0);
            float2 k23 = __half22float2(kh1);

            float part = fmaf(qs.x, k01.x,
                         fmaf(qs.y, k01.y,
                         fmaf(qs.z, k23.x,
                         fmaf(qs.w, k23.y, ler * ec))));
#pragma unroll
            for (int o = 16; o; o >>= 1)
                part += __shfl_xor_sync(FULLMASK, part, o);

            // unpack fp16 v
            __half2 h0 = *reinterpret_cast<__half2*>(&vu.x);
            __half2 h1 = *reinterpret_cast<__half2*>(&vu.y);
            float2 v01 = __half22float2(h0);
            float2 v23 = __half22float2(h1);

            // branch 0: online softmax of s0
            float nm0 = fmaxf(m0, part);
            float sc0 = __expf(m0 - nm0);
            float w0  = __expf(part - nm0);
            z0   = fmaf(z0, sc0, w0);
            a0.x = fmaf(a0.x, sc0, w0 * v01.x);
            a0.y = fmaf(a0.y, sc0, w0 * v01.y);
            a0.z = fmaf(a0.z, sc0, w0 * v23.x);
            a0.w = fmaf(a0.w, sc0, w0 * v23.y);
            m0 = nm0;

            // branch 1: online softmax of c*adj
            float s1  = c * adj;
            float nm1 = fmaxf(m1, s1);
            float sc1 = __expf(m1 - nm1);
            float w1  = __expf(s1 - nm1);
            z1   = fmaf(z1, sc1, w1);
            a1.x = fmaf(a1.x, sc1, w1 * v01.x);
            a1.y = fmaf(a1.y, sc1, w1 * v01.y);
            a1.z = fmaf(a1.z, sc1, w1 * v23.x);
            a1.w = fmaf(a1.w, sc1, w1 * v23.y);
            m1 = nm1;

            ku = ku2; ec = ec2; vu = vu2;
        }
    }

    float i0 = 0.5f / z0;
    float i1 = 0.5f / z1;
    float4 o;
    o.x = fmaf(a0.x, i0, a1.x * i1);
    o.y = fmaf(a0.y, i0, a1.y * i1);
    o.z = fmaf(a0.z, i0, a1.z * i1);
    o.w = fmaf(a0.w, i0, a1.w * i1);
    __stcs(&out4[wid * 32 + lane], o);
}

// ---------------------------------------------------------------------------
extern "C" void kernel_launch(void* const* d_in, const int* in_sizes, int n_in,
                              void* d_out, int out_size) {
    const float* q       = (const float*)d_in[0];
    const float* k       = (const float*)d_in[1];
    const float* v       = (const float*)d_in[2];
    const float* eigs    = (const float*)d_in[3];
    const float* adj     = (const float*)d_in[4];
    const float* lambda0 = (const float*)d_in[5];
    const float* gamma   = (const float*)d_in[6];
    const float* memb    = (const float*)d_in[7];
    const int*   row     = (const int*)d_in[8];
    const int*   col     = (const int*)d_in[9];
    const int*   mids    = (const int*)d_in[10];

    int n = in_sizes[10];  // N
    int e = in_sizes[8];   // E

    k_init<<<(n + 255) / 256, 256>>>(memb, mids, n);
    k_pack<<<2048, 256>>>((const float4*)k, (const float4*)v, n * 32);
    k_edge1<<<2048, 256>>>(row, col, e);
    k_scan_a<<<SCAN_BLOCKS, SCAN_THREADS>>>(n);
    k_scan_b<<<1, SCAN_BLOCKS>>>(lambda0, gamma, n, e);
    k_scan_c<<<SCAN_BLOCKS, SCAN_THREADS>>>(n);
    k_scatter<<<2048, 256>>>(row, col, adj, e);
    k_main<<<(n * 32 + 255) / 256, 256>>>(
        (const float4*)q, eigs, (float4*)d_out, n, e);
}

// round 12
// speedup vs baseline: 2.6313x; 1.1389x over previous
#include <cuda_runtime.h>
#include <cuda_fp16.h>
#include <math.h>

// Problem-fixed sizes: N=100000, E=1600000, D=128, EIG=32.
#define MAXN 100000
#define MAXE 1600000
#define FULLMASK 0xffffffffu
#define SCAN_BLOCKS 128
#define SCAN_THREADS 1024

// Scratch (device globals — explicitly zeroed by k_init every call).
__device__ float g_me[MAXN];
__device__ int   g_cnt[MAXN];
__device__ int   g_off[MAXN + 1];
__device__ float g_acc[3];
__device__ float g_par[2];          // [0]=exp(lambda0), [1]=c = gamma*sim
__device__ int2  g_edge[MAXE];      // (col, adj-as-int) sorted by row
__device__ uint2 g_vh[MAXN * 32];   // v fp16: lane layout, 4 halfs per uint2
__device__ uint4 g_kh4[MAXN * 16];  // k fp16: 8 halfs per uint4 (16-lane layout)
__device__ int   g_bsum[SCAN_BLOCKS];
__device__ int   g_bbase[SCAN_BLOCKS];

// ---- cache-policy-steered load helpers ----
__device__ __forceinline__ unsigned long long mk_policy_el() {
    unsigned long long pol;
    asm("createpolicy.fractional.L2::evict_last.b64 %0, 1.0;" : "=l"(pol));
    return pol;
}
__device__ __forceinline__ float2 ldg_el_f2(const float2* p,
                                            unsigned long long pol) {
    float2 r;
    asm("ld.global.nc.L2::cache_hint.v2.f32 {%0,%1},[%2],%3;"
        : "=f"(r.x), "=f"(r.y) : "l"(p), "l"(pol));
    return r;
}
__device__ __forceinline__ uint2 ldg_el_u2(const uint2* p,
                                           unsigned long long pol) {
    uint2 r;
    asm("ld.global.nc.L2::cache_hint.v2.u32 {%0,%1},[%2],%3;"
        : "=r"(r.x), "=r"(r.y) : "l"(p), "l"(pol));
    return r;
}
__device__ __forceinline__ uint4 ldg_el_u4(const uint4* p,
                                           unsigned long long pol) {
    uint4 r;
    asm("ld.global.nc.L2::cache_hint.v4.u32 {%0,%1,%2,%3},[%4],%5;"
        : "=r"(r.x), "=r"(r.y), "=r"(r.z), "=r"(r.w) : "l"(p), "l"(pol));
    return r;
}

// ---------------------------------------------------------------------------
__global__ void k_init(const float* __restrict__ memb,
                       const int* __restrict__ mids, int n) {
    int i = blockIdx.x * blockDim.x + threadIdx.x;
    if (i == 0) { g_acc[0] = 0.f; g_acc[1] = 0.f; g_acc[2] = 0.f; }
    if (i < n) {
        g_me[i]  = memb[__ldcs(&mids[i])];
        g_cnt[i] = 0;
    }
}

// ---------------------------------------------------------------------------
// K0b: pack k (uint4/8-half records) and v (uint2/4-half records) into fp16
// ---------------------------------------------------------------------------
__global__ void k_pack(const float4* __restrict__ k4,
                       const float4* __restrict__ v4, int n) {
    int n16 = n * 16, n32 = n * 32;
    for (int i = blockIdx.x * blockDim.x + threadIdx.x; i < n16;
         i += gridDim.x * blockDim.x) {
        float4 a = __ldcs(&k4[2 * i]);
        float4 b = __ldcs(&k4[2 * i + 1]);
        __half2 h0 = __floats2half2_rn(a.x, a.y);
        __half2 h1 = __floats2half2_rn(a.z, a.w);
        __half2 h2 = __floats2half2_rn(b.x, b.y);
        __half2 h3 = __floats2half2_rn(b.z, b.w);
        uint4 u;
        u.x = *reinterpret_cast<unsigned*>(&h0);
        u.y = *reinterpret_cast<unsigned*>(&h1);
        u.z = *reinterpret_cast<unsigned*>(&h2);
        u.w = *reinterpret_cast<unsigned*>(&h3);
        g_kh4[i] = u;
    }
    for (int i = blockIdx.x * blockDim.x + threadIdx.x; i < n32;
         i += gridDim.x * blockDim.x) {
        float4 vv = __ldcs(&v4[i]);
        __half2 h0 = __floats2half2_rn(vv.x, vv.y);
        __half2 h1 = __floats2half2_rn(vv.z, vv.w);
        uint2 u;
        u.x = *reinterpret_cast<unsigned*>(&h0);
        u.y = *reinterpret_cast<unsigned*>(&h1);
        g_vh[i] = u;
    }
}

// ---------------------------------------------------------------------------
__global__ void k_edge1(const int* __restrict__ row,
                        const int* __restrict__ col, int e) {
    float pab = 0.f, pa2 = 0.f, pb2 = 0.f;
    for (int i = blockIdx.x * blockDim.x + threadIdx.x; i < e;
         i += gridDim.x * blockDim.x) {
        int r = __ldcs(&row[i]), c = __ldcs(&col[i]);
        atomicAdd(&g_cnt[r], 1);
        float a = g_me[r], b = g_me[c];
        pab = fmaf(a, b, pab);
        pa2 = fmaf(a, a, pa2);
        pb2 = fmaf(b, b, pb2);
    }
#pragma unroll
    for (int o = 16; o; o >>= 1) {
        pab += __shfl_down_sync(FULLMASK, pab, o);
        pa2 += __shfl_down_sync(FULLMASK, pa2, o);
        pb2 += __shfl_down_sync(FULLMASK, pb2, o);
    }
    __shared__ float sb[3][8];
    int w = threadIdx.x >> 5, l = threadIdx.x & 31;
    if (!l) { sb[0][w] = pab; sb[1][w] = pa2; sb[2][w] = pb2; }
    __syncthreads();
    if (!threadIdx.x) {
        float t0 = 0.f, t1 = 0.f, t2 = 0.f;
        int nw = blockDim.x >> 5;
        for (int j = 0; j < nw; j++) { t0 += sb[0][j]; t1 += sb[1][j]; t2 += sb[2][j]; }
        atomicAdd(&g_acc[0], t0);
        atomicAdd(&g_acc[1], t1);
        atomicAdd(&g_acc[2], t2);
    }
}

// ---------------------------------------------------------------------------
__global__ void k_scan_a(int n) {
    __shared__ int wsum[32];
    int t = threadIdx.x, lane = t & 31, warp = t >> 5;
    int i = blockIdx.x * SCAN_THREADS + t;
    int v = (i < n) ? g_cnt[i] : 0;
    int s = v;
#pragma unroll
    for (int o = 16; o; o >>= 1) s += __shfl_down_sync(FULLMASK, s, o);
    if (!lane) wsum[warp] = s;
    __syncthreads();
    if (warp == 0) {
        int x = wsum[lane];
#pragma unroll
        for (int o = 16; o; o >>= 1) x += __shfl_down_sync(FULLMASK, x, o);
        if (!lane) g_bsum[blockIdx.x] = x;
    }
}

__global__ void k_scan_b(const float* __restrict__ lambda0,
                         const float* __restrict__ gamma, int n, int e) {
    __shared__ int ws[4];
    int t = threadIdx.x, lane = t & 31, warp = t >> 5;   // 128 threads
    int v = g_bsum[t];
    int inc = v;
#pragma unroll
    for (int o = 1; o < 32; o <<= 1) {
        int u = __shfl_up_sync(FULLMASK, inc, o);
        if (lane >= o) inc += u;
    }
    if (lane == 31) ws[warp] = inc;
    __syncthreads();
    if (t == 0) {
        int run = 0;
        for (int j = 0; j < 4; j++) { int x = ws[j]; ws[j] = run; run += x; }
        g_off[n] = e;
        float sab = g_acc[0], sa2 = g_acc[1], sb2 = g_acc[2];
        float na = fmaxf(sqrtf(sa2), 1e-8f);
        float nb = fmaxf(sqrtf(sb2), 1e-8f);
        g_par[0] = expf(lambda0[0]);
        g_par[1] = gamma[0] * (sab / (na * nb));
    }
    __syncthreads();
    g_bbase[t] = ws[warp] + (inc - v);
}

__global__ void k_scan_c(int n) {
    __shared__ int wsum[32];
    int t = threadIdx.x, lane = t & 31, warp = t >> 5;
    int i = blockIdx.x * SCAN_THREADS + t;
    int v = (i < n) ? g_cnt[i] : 0;
    int inc = v;
#pragma unroll
    for (int o = 1; o < 32; o <<= 1) {
        int u = __shfl_up_sync(FULLMASK, inc, o);
        if (lane >= o) inc += u;
    }
    if (lane == 31) wsum[warp] = inc;
    __syncthreads();
    if (warp == 0) {
        int x = wsum[lane];
        int winc = x;
#pragma unroll
        for (int o = 1; o < 32; o <<= 1) {
            int u = __shfl_up_sync(FULLMASK, winc, o);
            if (lane >= o) winc += u;
        }
        wsum[lane] = winc - x;
    }
    __syncthreads();
    int run = g_bbase[blockIdx.x] + wsum[warp] + (inc - v);
    if (i < n) {
        g_off[i] = run;
        g_cnt[i] = run;
    }
}

// ---------------------------------------------------------------------------
__global__ void k_scatter(const int* __restrict__ row,
                          const int* __restrict__ col,
                          const float* __restrict__ adj, int e) {
    for (int i = blockIdx.x * blockDim.x + threadIdx.x; i < e;
         i += gridDim.x * blockDim.x) {
        int pos = atomicAdd(&g_cnt[__ldcs(&row[i])], 1);
        pos = min(max(pos, 0), MAXE - 1);
        g_edge[pos] = make_int2(__ldcs(&col[i]), __float_as_int(__ldcs(&adj[i])));
    }
}

// ---------------------------------------------------------------------------
// K4: DUAL-EDGE per-row kernel. Lanes 0-15 own edge A, 16-31 own edge B;
// each lane covers 8 k-halfs (uint4) + 2 eigs (float2). Score reduce =
// xor{1,2,4,8} within 16-lane group (4 shuffles for BOTH edges) + xor16 swap.
// Paired online-softmax merge: 3 exps per branch per pair. All shuffles
// full-warp unconditional; odd tail killed via s=-INF under uniform flag.
// ---------------------------------------------------------------------------
__global__ void __launch_bounds__(256)
k_main(const float4* __restrict__ q4, const float2* __restrict__ eig2,
       float4* __restrict__ out4, int n, int e) {
    int wid  = (blockIdx.x * blockDim.x + threadIdx.x) >> 5;
    int lane = threadIdx.x & 31;
    if (wid >= n) return;
    int start = g_off[wid];
    int end   = g_off[wid + 1];
    start = min(max(start, 0), e);
    end   = min(max(end, start), e);

    float4 zero = make_float4(0.f, 0.f, 0.f, 0.f);
    if (start == end) {
        out4[wid * 32 + lane] = zero;
        return;
    }
    unsigned long long pol = mk_policy_el();
    const float inv = 0.08838834764831845f;  // 1/sqrt(128)
    float c   = g_par[1];
    float lam = g_par[0];
    int  sub  = lane & 15;
    int  grp  = lane >> 4;        // 0 = edge A, 1 = edge B

    // lane sub owns q elements [8s,8s+8) and eig elements [2s,2s+1)
    float4 qa = __ldcs(&q4[wid * 32 + 2 * sub]);
    float4 qb = __ldcs(&q4[wid * 32 + 2 * sub + 1]);
    qa.x *= inv; qa.y *= inv; qa.z *= inv; qa.w *= inv;
    qb.x *= inv; qb.y *= inv; qb.z *= inv; qb.w *= inv;
    float2 er = ldg_el_f2(&eig2[wid * 16 + sub], pol);
    float lerx = lam * er.x, lery = lam * er.y;

    float  m0 = -INFINITY, z0 = 0.f;
    float  m1 = -INFINITY, z1 = 0.f;
    float4 a0 = zero, a1 = zero;

    for (int base = start; base < end; base += 32) {
        int nb = end - base; if (nb > 32) nb = 32;
        int2 ea = (lane < nb) ? __ldcs(&g_edge[base + lane]) : make_int2(0, 0);
        int   bc = min(max(ea.x, 0), n - 1);
        float ba = __int_as_float(ea.y);

        for (int t = 0; 2 * t < nb; t++) {      // warp-uniform trip count
            int iA = 2 * t, iB = 2 * t + 1;
            bool hasB = iB < nb;                // warp-uniform
            int   cA   = __shfl_sync(FULLMASK, bc, iA);
            int   cB   = __shfl_sync(FULLMASK, bc, iB);
            float adjA = __shfl_sync(FULLMASK, ba, iA);
            float adjB = __shfl_sync(FULLMASK, ba, iB);
            int   cg   = grp ? cB : cA;         // my group's edge col

            uint4  ku = ldg_el_u4(&g_kh4[cg * 16 + sub], pol);
            float2 ec = ldg_el_f2(&eig2[cg * 16 + sub], pol);
            uint2  vuA = ldg_el_u2(&g_vh[cA * 32 + lane], pol);
            uint2  vuB = ldg_el_u2(&g_vh[cB * 32 + lane], pol);

            // unpack 8 fp16 k values
            __half2 h0 = *reinterpret_cast<__half2*>(&ku.x);
            __half2 h1 = *reinterpret_cast<__half2*>(&ku.y);
            __half2 h2 = *reinterpret_cast<__half2*>(&ku.z);
            __half2 h3 = *reinterpret_cast<__half2*>(&ku.w);
            float2 k01 = __half22float2(h0);
            float2 k23 = __half22float2(h1);
            float2 k45 = __half22float2(h2);
            float2 k67 = __half22float2(h3);

            float part = fmaf(qa.x, k01.x,
                         fmaf(qa.y, k01.y,
                         fmaf(qa.z, k23.x,
                         fmaf(qa.w, k23.y,
                         fmaf(qb.x, k45.x,
                         fmaf(qb.y, k45.y,
                         fmaf(qb.z, k67.x,
                         fmaf(qb.w, k67.y,
                         fmaf(lerx, ec.x, lery * ec.y)))))))));
            // reduce within 16-lane group (both edges at once)
            part += __shfl_xor_sync(FULLMASK, part, 1);
            part += __shfl_xor_sync(FULLMASK, part, 2);
            part += __shfl_xor_sync(FULLMASK, part, 4);
            part += __shfl_xor_sync(FULLMASK, part, 8);
            float so = __shfl_xor_sync(FULLMASK, part, 16);
            float sA = grp ? so : part;
            float sB = grp ? part : so;
            if (!hasB) sB = -INFINITY;          // uniform

            // unpack fp16 v for both edges
            __half2 a0h = *reinterpret_cast<__half2*>(&vuA.x);
            __half2 a1h = *reinterpret_cast<__half2*>(&vuA.y);
            __half2 b0h = *reinterpret_cast<__half2*>(&vuB.x);
            __half2 b1h = *reinterpret_cast<__half2*>(&vuB.y);
            float2 vA01 = __half22float2(a0h);
            float2 vA23 = __half22float2(a1h);
            float2 vB01 = __half22float2(b0h);
            float2 vB23 = __half22float2(b1h);

            // branch 0: paired online softmax merge
            float nm0 = fmaxf(m0, fmaxf(sA, sB));
            float f0  = __expf(m0 - nm0);
            float wA0 = __expf(sA - nm0);
            float wB0 = __expf(sB - nm0);       // 0 if !hasB
            z0   = fmaf(z0, f0, wA0 + wB0);
            a0.x = fmaf(a0.x, f0, fmaf(wA0, vA01.x, wB0 * vB01.x));
            a0.y = fmaf(a0.y, f0, fmaf(wA0, vA01.y, wB0 * vB01.y));
            a0.z = fmaf(a0.z, f0, fmaf(wA0, vA23.x, wB0 * vB23.x));
            a0.w = fmaf(a0.w, f0, fmaf(wA0, vA23.y, wB0 * vB23.y));
            m0 = nm0;

            // branch 1
            float s1A = c * adjA;
            float s1B = hasB ? c * adjB : -INFINITY;
            float nm1 = fmaxf(m1, fmaxf(s1A, s1B));
            float f1  = __expf(m1 - nm1);
            float wA1 = __expf(s1A - nm1);
            float wB1 = __expf(s1B - nm1);
            z1   = fmaf(z1, f1, wA1 + wB1);
            a1.x = fmaf(a1.x, f1, fmaf(wA1, vA01.x, wB1 * vB01.x));
            a1.y = fmaf(a1.y, f1, fmaf(wA1, vA01.y, wB1 * vB01.y));
            a1.z = fmaf(a1.z, f1, fmaf(wA1, vA23.x, wB1 * vB23.x));
            a1.w = fmaf(a1.w, f1, fmaf(wA1, vA23.y, wB1 * vB23.y));
            m1 = nm1;
        }
    }

    float i0 = 0.5f / z0;
    float i1 = 0.5f / z1;
    float4 o;
    o.x = fmaf(a0.x, i0, a1.x * i1);
    o.y = fmaf(a0.y, i0, a1.y * i1);
    o.z = fmaf(a0.z, i0, a1.z * i1);
    o.w = fmaf(a0.w, i0, a1.w * i1);
    __stcs(&out4[wid * 32 + lane], o);
}

// ---------------------------------------------------------------------------
extern "C" void kernel_launch(void* const* d_in, const int* in_sizes, int n_in,
                              void* d_out, int out_size) {
    const float* q       = (const float*)d_in[0];
    const float* k       = (const float*)d_in[1];
    const float* v       = (const float*)d_in[2];
    const float* eigs    = (const float*)d_in[3];
    const float* adj     = (const float*)d_in[4];
    const float* lambda0 = (const float*)d_in[5];
    const float* gamma   = (const float*)d_in[6];
    const float* memb    = (const float*)d_in[7];
    const int*   row     = (const int*)d_in[8];
    const int*   col     = (const int*)d_in[9];
    const int*   mids    = (const int*)d_in[10];

    int n = in_sizes[10];  // N
    int e = in_sizes[8];   // E

    k_init<<<(n + 255) / 256, 256>>>(memb, mids, n);
    k_pack<<<2048, 256>>>((const float4*)k, (const float4*)v, n);
    k_edge1<<<2048, 256>>>(row, col, e);
    k_scan_a<<<SCAN_BLOCKS, SCAN_THREADS>>>(n);
    k_scan_b<<<1, SCAN_BLOCKS>>>(lambda0, gamma, n, e);
    k_scan_c<<<SCAN_BLOCKS, SCAN_THREADS>>>(n);
    k_scatter<<<2048, 256>>>(row, col, adj, e);
    k_main<<<(n * 32 + 255) / 256, 256>>>(
        (const float4*)q, (const float2*)eigs, (float4*)d_out, n, e);
}

// round 13
// speedup vs baseline: 2.6514x; 1.0077x over previous
#include <cuda_runtime.h>
#include <cuda_fp16.h>
#include <math.h>

// Problem-fixed sizes: N=100000, E=1600000, D=128, EIG=32.
#define MAXN 100000
#define MAXE 1600000
#define FULLMASK 0xffffffffu
#define SCAN_BLOCKS 128
#define SCAN_THREADS 1024

// Scratch (device globals — explicitly zeroed by k_init every call).
__device__ float g_me[MAXN];
__device__ int   g_cnt[MAXN];
__device__ int   g_off[MAXN + 1];
__device__ float g_acc[3];
__device__ float g_par[2];          // [0]=exp(lambda0), [1]=c = gamma*sim
__device__ int2  g_edge[MAXE];      // (col, adj-as-int) sorted by row
__device__ uint2 g_vh[MAXN * 32];   // v fp16: lane layout, 4 halfs per uint2
__device__ uint4 g_kh4[MAXN * 16];  // k fp16: 8 halfs per uint4 (16-lane layout)
__device__ int   g_bsum[SCAN_BLOCKS];
__device__ int   g_bbase[SCAN_BLOCKS];

// ---- cache-policy-steered load helpers ----
__device__ __forceinline__ unsigned long long mk_policy_el() {
    unsigned long long pol;
    asm("createpolicy.fractional.L2::evict_last.b64 %0, 1.0;" : "=l"(pol));
    return pol;
}
__device__ __forceinline__ float2 ldg_el_f2(const float2* p,
                                            unsigned long long pol) {
    float2 r;
    asm("ld.global.nc.L2::cache_hint.v2.f32 {%0,%1},[%2],%3;"
        : "=f"(r.x), "=f"(r.y) : "l"(p), "l"(pol));
    return r;
}
__device__ __forceinline__ uint2 ldg_el_u2(const uint2* p,
                                           unsigned long long pol) {
    uint2 r;
    asm("ld.global.nc.L2::cache_hint.v2.u32 {%0,%1},[%2],%3;"
        : "=r"(r.x), "=r"(r.y) : "l"(p), "l"(pol));
    return r;
}
__device__ __forceinline__ uint4 ldg_el_u4(const uint4* p,
                                           unsigned long long pol) {
    uint4 r;
    asm("ld.global.nc.L2::cache_hint.v4.u32 {%0,%1,%2,%3},[%4],%5;"
        : "=r"(r.x), "=r"(r.y), "=r"(r.z), "=r"(r.w) : "l"(p), "l"(pol));
    return r;
}

// ---------------------------------------------------------------------------
// K0: zero counters/accumulators, compute me[n]
// ---------------------------------------------------------------------------
__global__ void k_init(const float* __restrict__ memb,
                       const int* __restrict__ mids, int n) {
    int i = blockIdx.x * blockDim.x + threadIdx.x;
    if (i == 0) { g_acc[0] = 0.f; g_acc[1] = 0.f; g_acc[2] = 0.f; }
    if (i < n) {
        g_me[i]  = memb[__ldcs(&mids[i])];
        g_cnt[i] = 0;
    }
}

// ---------------------------------------------------------------------------
// K0b: pack k (uint4/8-half records) and v (uint2/4-half records) into fp16
// ---------------------------------------------------------------------------
__global__ void k_pack(const float4* __restrict__ k4,
                       const float4* __restrict__ v4, int n) {
    int n16 = n * 16, n32 = n * 32;
    for (int i = blockIdx.x * blockDim.x + threadIdx.x; i < n16;
         i += gridDim.x * blockDim.x) {
        float4 a = __ldcs(&k4[2 * i]);
        float4 b = __ldcs(&k4[2 * i + 1]);
        __half2 h0 = __floats2half2_rn(a.x, a.y);
        __half2 h1 = __floats2half2_rn(a.z, a.w);
        __half2 h2 = __floats2half2_rn(b.x, b.y);
        __half2 h3 = __floats2half2_rn(b.z, b.w);
        uint4 u;
        u.x = *reinterpret_cast<unsigned*>(&h0);
        u.y = *reinterpret_cast<unsigned*>(&h1);
        u.z = *reinterpret_cast<unsigned*>(&h2);
        u.w = *reinterpret_cast<unsigned*>(&h3);
        g_kh4[i] = u;
    }
    for (int i = blockIdx.x * blockDim.x + threadIdx.x; i < n32;
         i += gridDim.x * blockDim.x) {
        float4 vv = __ldcs(&v4[i]);
        __half2 h0 = __floats2half2_rn(vv.x, vv.y);
        __half2 h1 = __floats2half2_rn(vv.z, vv.w);
        uint2 u;
        u.x = *reinterpret_cast<unsigned*>(&h0);
        u.y = *reinterpret_cast<unsigned*>(&h1);
        g_vh[i] = u;
    }
}

// ---------------------------------------------------------------------------
// K1: pure row histogram (reads ONLY row — scalar reduction moved to scatter)
// ---------------------------------------------------------------------------
__global__ void k_hist(const int* __restrict__ row, int e) {
    for (int i = blockIdx.x * blockDim.x + threadIdx.x; i < e;
         i += gridDim.x * blockDim.x) {
        atomicAdd(&g_cnt[__ldcs(&row[i])], 1);
    }
}

// ---------------------------------------------------------------------------
// Scan stage A: per-block COALESCED reduce of g_cnt.
// ---------------------------------------------------------------------------
__global__ void k_scan_a(int n) {
    __shared__ int wsum[32];
    int t = threadIdx.x, lane = t & 31, warp = t >> 5;
    int i = blockIdx.x * SCAN_THREADS + t;
    int v = (i < n) ? g_cnt[i] : 0;
    int s = v;
#pragma unroll
    for (int o = 16; o; o >>= 1) s += __shfl_down_sync(FULLMASK, s, o);
    if (!lane) wsum[warp] = s;
    __syncthreads();
    if (warp == 0) {
        int x = wsum[lane];
#pragma unroll
        for (int o = 16; o; o >>= 1) x += __shfl_down_sync(FULLMASK, x, o);
        if (!lane) g_bsum[blockIdx.x] = x;
    }
}

// ---------------------------------------------------------------------------
// Scan stage B: one tiny block scans the 128 block sums.
// ---------------------------------------------------------------------------
__global__ void k_scan_b(int n, int e) {
    __shared__ int ws[4];
    int t = threadIdx.x, lane = t & 31, warp = t >> 5;   // 128 threads
    int v = g_bsum[t];
    int inc = v;
#pragma unroll
    for (int o = 1; o < 32; o <<= 1) {
        int u = __shfl_up_sync(FULLMASK, inc, o);
        if (lane >= o) inc += u;
    }
    if (lane == 31) ws[warp] = inc;
    __syncthreads();
    if (t == 0) {
        int run = 0;
        for (int j = 0; j < 4; j++) { int x = ws[j]; ws[j] = run; run += x; }
        g_off[n] = e;
    }
    __syncthreads();
    g_bbase[t] = ws[warp] + (inc - v);
}

// ---------------------------------------------------------------------------
// Scan stage C: per-block COALESCED exclusive scan + base -> g_off, cursor.
// ---------------------------------------------------------------------------
__global__ void k_scan_c(int n) {
    __shared__ int wsum[32];
    int t = threadIdx.x, lane = t & 31, warp = t >> 5;
    int i = blockIdx.x * SCAN_THREADS + t;
    int v = (i < n) ? g_cnt[i] : 0;
    int inc = v;
#pragma unroll
    for (int o = 1; o < 32; o <<= 1) {
        int u = __shfl_up_sync(FULLMASK, inc, o);
        if (lane >= o) inc += u;
    }
    if (lane == 31) wsum[warp] = inc;
    __syncthreads();
    if (warp == 0) {
        int x = wsum[lane];
        int winc = x;
#pragma unroll
        for (int o = 1; o < 32; o <<= 1) {
            int u = __shfl_up_sync(FULLMASK, winc, o);
            if (lane >= o) winc += u;
        }
        wsum[lane] = winc - x;
    }
    __syncthreads();
    int run = g_bbase[blockIdx.x] + wsum[warp] + (inc - v);
    if (i < n) {
        g_off[i] = run;
        g_cnt[i] = run;
    }
}

// ---------------------------------------------------------------------------
// K3: counting-sort scatter + FUSED cosine-sim scalar reduction (absorbs the
// former k_edge1 E-sweep; me gathers hit the 400KB L2-resident g_me).
// ---------------------------------------------------------------------------
__global__ void k_scatter(const int* __restrict__ row,
                          const int* __restrict__ col,
                          const float* __restrict__ adj, int e) {
    float pab = 0.f, pa2 = 0.f, pb2 = 0.f;
    for (int i = blockIdx.x * blockDim.x + threadIdx.x; i < e;
         i += gridDim.x * blockDim.x) {
        int r = __ldcs(&row[i]), c = __ldcs(&col[i]);
        int pos = atomicAdd(&g_cnt[r], 1);
        pos = min(max(pos, 0), MAXE - 1);
        g_edge[pos] = make_int2(c, __float_as_int(__ldcs(&adj[i])));
        float a = g_me[r], b = g_me[c];
        pab = fmaf(a, b, pab);
        pa2 = fmaf(a, a, pa2);
        pb2 = fmaf(b, b, pb2);
    }
#pragma unroll
    for (int o = 16; o; o >>= 1) {
        pab += __shfl_down_sync(FULLMASK, pab, o);
        pa2 += __shfl_down_sync(FULLMASK, pa2, o);
        pb2 += __shfl_down_sync(FULLMASK, pb2, o);
    }
    __shared__ float sb[3][8];
    int w = threadIdx.x >> 5, l = threadIdx.x & 31;
    if (!l) { sb[0][w] = pab; sb[1][w] = pa2; sb[2][w] = pb2; }
    __syncthreads();
    if (!threadIdx.x) {
        float t0 = 0.f, t1 = 0.f, t2 = 0.f;
        int nw = blockDim.x >> 5;
        for (int j = 0; j < nw; j++) { t0 += sb[0][j]; t1 += sb[1][j]; t2 += sb[2][j]; }
        atomicAdd(&g_acc[0], t0);
        atomicAdd(&g_acc[1], t1);
        atomicAdd(&g_acc[2], t2);
    }
}

// ---------------------------------------------------------------------------
// K3b: tiny kernel — compute g_par scalars from g_acc (after scatter).
// ---------------------------------------------------------------------------
__global__ void k_par(const float* __restrict__ lambda0,
                      const float* __restrict__ gamma) {
    if (threadIdx.x == 0) {
        float sab = g_acc[0], sa2 = g_acc[1], sb2 = g_acc[2];
        float na = fmaxf(sqrtf(sa2), 1e-8f);
        float nb = fmaxf(sqrtf(sb2), 1e-8f);
        g_par[0] = expf(lambda0[0]);
        g_par[1] = gamma[0] * (sab / (na * nb));
    }
}

// ---------------------------------------------------------------------------
// K4: DUAL-EDGE per-row kernel (R12 verbatim — validated winner).
// ---------------------------------------------------------------------------
__global__ void __launch_bounds__(256)
k_main(const float4* __restrict__ q4, const float2* __restrict__ eig2,
       float4* __restrict__ out4, int n, int e) {
    int wid  = (blockIdx.x * blockDim.x + threadIdx.x) >> 5;
    int lane = threadIdx.x & 31;
    if (wid >= n) return;
    int start = g_off[wid];
    int end   = g_off[wid + 1];
    start = min(max(start, 0), e);
    end   = min(max(end, start), e);

    float4 zero = make_float4(0.f, 0.f, 0.f, 0.f);
    if (start == end) {
        out4[wid * 32 + lane] = zero;
        return;
    }
    unsigned long long pol = mk_policy_el();
    const float inv = 0.08838834764831845f;  // 1/sqrt(128)
    float c   = g_par[1];
    float lam = g_par[0];
    int  sub  = lane & 15;
    int  grp  = lane >> 4;        // 0 = edge A, 1 = edge B

    float4 qa = __ldcs(&q4[wid * 32 + 2 * sub]);
    float4 qb = __ldcs(&q4[wid * 32 + 2 * sub + 1]);
    qa.x *= inv; qa.y *= inv; qa.z *= inv; qa.w *= inv;
    qb.x *= inv; qb.y *= inv; qb.z *= inv; qb.w *= inv;
    float2 er = ldg_el_f2(&eig2[wid * 16 + sub], pol);
    float lerx = lam * er.x, lery = lam * er.y;

    float  m0 = -INFINITY, z0 = 0.f;
    float  m1 = -INFINITY, z1 = 0.f;
    float4 a0 = zero, a1 = zero;

    for (int base = start; base < end; base += 32) {
        int nb = end - base; if (nb > 32) nb = 32;
        int2 ea = (lane < nb) ? __ldcs(&g_edge[base + lane]) : make_int2(0, 0);
        int   bc = min(max(ea.x, 0), n - 1);
        float ba = __int_as_float(ea.y);

        for (int t = 0; 2 * t < nb; t++) {      // warp-uniform trip count
            int iA = 2 * t, iB = 2 * t + 1;
            bool hasB = iB < nb;                // warp-uniform
            int   cA   = __shfl_sync(FULLMASK, bc, iA);
            int   cB   = __shfl_sync(FULLMASK, bc, iB);
            float adjA = __shfl_sync(FULLMASK, ba, iA);
            float adjB = __shfl_sync(FULLMASK, ba, iB);
            int   cg   = grp ? cB : cA;

            uint4  ku = ldg_el_u4(&g_kh4[cg * 16 + sub], pol);
            float2 ec = ldg_el_f2(&eig2[cg * 16 + sub], pol);
            uint2  vuA = ldg_el_u2(&g_vh[cA * 32 + lane], pol);
            uint2  vuB = ldg_el_u2(&g_vh[cB * 32 + lane], pol);

            __half2 h0 = *reinterpret_cast<__half2*>(&ku.x);
            __half2 h1 = *reinterpret_cast<__half2*>(&ku.y);
            __half2 h2 = *reinterpret_cast<__half2*>(&ku.z);
            __half2 h3 = *reinterpret_cast<__half2*>(&ku.w);
            float2 k01 = __half22float2(h0);
            float2 k23 = __half22float2(h1);
            float2 k45 = __half22float2(h2);
            float2 k67 = __half22float2(h3);

            float part = fmaf(qa.x, k01.x,
                         fmaf(qa.y, k01.y,
                         fmaf(qa.z, k23.x,
                         fmaf(qa.w, k23.y,
                         fmaf(qb.x, k45.x,
                         fmaf(qb.y, k45.y,
                         fmaf(qb.z, k67.x,
                         fmaf(qb.w, k67.y,
                         fmaf(lerx, ec.x, lery * ec.y)))))))));
            part += __shfl_xor_sync(FULLMASK, part, 1);
            part += __shfl_xor_sync(FULLMASK, part, 2);
            part += __shfl_xor_sync(FULLMASK, part, 4);
            part += __shfl_xor_sync(FULLMASK, part, 8);
            float so = __shfl_xor_sync(FULLMASK, part, 16);
            float sA = grp ? so : part;
            float sB = grp ? part : so;
            if (!hasB) sB = -INFINITY;

            __half2 a0h = *reinterpret_cast<__half2*>(&vuA.x);
            __half2 a1h = *reinterpret_cast<__half2*>(&vuA.y);
            __half2 b0h = *reinterpret_cast<__half2*>(&vuB.x);
            __half2 b1h = *reinterpret_cast<__half2*>(&vuB.y);
            float2 vA01 = __half22float2(a0h);
            float2 vA23 = __half22float2(a1h);
            float2 vB01 = __half22float2(b0h);
            float2 vB23 = __half22float2(b1h);

            float nm0 = fmaxf(m0, fmaxf(sA, sB));
            float f0  = __expf(m0 - nm0);
            float wA0 = __expf(sA - nm0);
            float wB0 = __expf(sB - nm0);
            z0   = fmaf(z0, f0, wA0 + wB0);
            a0.x = fmaf(a0.x, f0, fmaf(wA0, vA01.x, wB0 * vB01.x));
            a0.y = fmaf(a0.y, f0, fmaf(wA0, vA01.y, wB0 * vB01.y));
            a0.z = fmaf(a0.z, f0, fmaf(wA0, vA23.x, wB0 * vB23.x));
            a0.w = fmaf(a0.w, f0, fmaf(wA0, vA23.y, wB0 * vB23.y));
            m0 = nm0;

            float s1A = c * adjA;
            float s1B = hasB ? c * adjB : -INFINITY;
            float nm1 = fmaxf(m1, fmaxf(s1A, s1B));
            float f1  = __expf(m1 - nm1);
            float wA1 = __expf(s1A - nm1);
            float wB1 = __expf(s1B - nm1);
            z1   = fmaf(z1, f1, wA1 + wB1);
            a1.x = fmaf(a1.x, f1, fmaf(wA1, vA01.x, wB1 * vB01.x));
            a1.y = fmaf(a1.y, f1, fmaf(wA1, vA01.y, wB1 * vB01.y));
            a1.z = fmaf(a1.z, f1, fmaf(wA1, vA23.x, wB1 * vB23.x));
            a1.w = fmaf(a1.w, f1, fmaf(wA1, vA23.y, wB1 * vB23.y));
            m1 = nm1;
        }
    }

    float i0 = 0.5f / z0;
    float i1 = 0.5f / z1;
    float4 o;
    o.x = fmaf(a0.x, i0, a1.x * i1);
    o.y = fmaf(a0.y, i0, a1.y * i1);
    o.z = fmaf(a0.z, i0, a1.z * i1);
    o.w = fmaf(a0.w, i0, a1.w * i1);
    __stcs(&out4[wid * 32 + lane], o);
}

// ---------------------------------------------------------------------------
extern "C" void kernel_launch(void* const* d_in, const int* in_sizes, int n_in,
                              void* d_out, int out_size) {
    const float* q       = (const float*)d_in[0];
    const float* k       = (const float*)d_in[1];
    const float* v       = (const float*)d_in[2];
    const float* eigs    = (const float*)d_in[3];
    const float* adj     = (const float*)d_in[4];
    const float* lambda0 = (const float*)d_in[5];
    const float* gamma   = (const float*)d_in[6];
    const float* memb    = (const float*)d_in[7];
    const int*   row     = (const int*)d_in[8];
    const int*   col     = (const int*)d_in[9];
    const int*   mids    = (const int*)d_in[10];

    int n = in_sizes[10];  // N
    int e = in_sizes[8];   // E

    k_init<<<(n + 255) / 256, 256>>>(memb, mids, n);
    k_pack<<<2048, 256>>>((const float4*)k, (const float4*)v, n);
    k_hist<<<2048, 256>>>(row, e);
    k_scan_a<<<SCAN_BLOCKS, SCAN_THREADS>>>(n);
    k_scan_b<<<1, SCAN_BLOCKS>>>(n, e);
    k_scan_c<<<SCAN_BLOCKS, SCAN_THREADS>>>(n);
    k_scatter<<<2048, 256>>>(row, col, adj, e);
    k_par<<<1, 32>>>(lambda0, gamma);
    k_main<<<(n * 32 + 255) / 256, 256>>>(
        (const float4*)q, (const float2*)eigs, (float4*)d_out, n, e);
}